// round 4
// baseline (speedup 1.0000x reference)
#include <cuda_runtime.h>
#include <stdint.h>

// PNLoss: prototypical-network leave-one-out loss.
// S=8192, N=2048, D=128, C=256 (32 members/class).
// logit[n,c] = -0.5*( q2 - 2*(s - del*q2)/den + (m2 - del*(2s - q2))/den^2 ),
//   s = xq[n].mus[c], den = max(cnt-del, 0.1), masked 0 when cnt-del <= 0.1.
// loss = mean_n( lse_c(logit) - logit[n, y_n] ).

#define S_MAX 8192
#define N_MAX 2048
#define DIM   128
#define NC    256
#define CAP   40
#define QB    4              // queries per k2 block
#define K2T   128            // k2 threads
#define MAXBLK (N_MAX / QB)  // 512

__device__ int   g_ys32[S_MAX];
__device__ int   g_pos32[N_MAX];
__device__ int   g_members[NC * CAP];
__device__ int   g_cnt[NC];          // zero at load; k1 re-zeros each call
__device__ float g_cntf[NC];
__device__ float g_mus2[DIM * NC];   // [d][c] layout: class pairs contiguous
__device__ float g_m2[NC];
__device__ float g_part[MAXBLK];
__device__ int   g_ticket;           // zero at load; k2 last block resets

// ---------------------------------------------------------------------------
// k_build: dtype detect (int32 vs int64), normalize, member scatter.
// ---------------------------------------------------------------------------
__global__ void k_build(const void* __restrict__ ys_raw,
                        const void* __restrict__ pos_raw,
                        int S, int N)
{
    __shared__ int s_ys64, s_pos64;
    int t = threadIdx.x;
    if (t == 0) { s_ys64 = 1; s_pos64 = 1; }
    __syncthreads();
    if (t < 64 && t < S && t < N) {
        long long v = ((const long long*)ys_raw)[t];
        if (v < 0 || v >= NC) s_ys64 = 0;
        long long p = ((const long long*)pos_raw)[t];
        if (p < 0 || p >= S) s_pos64 = 0;
    }
    __syncthreads();
    const int ys64 = s_ys64, pos64 = s_pos64;

    int stride = gridDim.x * blockDim.x;
    for (int i = blockIdx.x * blockDim.x + t; i < S; i += stride) {
        int v = ys64 ? (int)((const long long*)ys_raw)[i]
                     : ((const int*)ys_raw)[i];
        g_ys32[i] = v;
        if (v >= 0 && v < NC) {
            int slot = atomicAdd(&g_cnt[v], 1);
            if (slot < CAP) g_members[v * CAP + slot] = i;
        }
    }
    for (int i = blockIdx.x * blockDim.x + t; i < N; i += stride) {
        int v = pos64 ? (int)((const long long*)pos_raw)[i]
                      : ((const int*)pos_raw)[i];
        g_pos32[i] = v;
    }
}

// ---------------------------------------------------------------------------
// k1_protos: class prototype sums + ||mu||^2 into [d][c] layout.
// Warp 0 bitonic-sorts members -> canonical fp32 summation order.
// Re-zeros g_cnt for the next graph replay.
// ---------------------------------------------------------------------------
__global__ void k1_protos(const float* __restrict__ xs)
{
    __shared__ int   s_mem[CAP];
    __shared__ float wsum[4];
    int c = blockIdx.x;
    int t = threadIdx.x;
    int cnt = g_cnt[c]; if (cnt > CAP) cnt = CAP;

    if (t < 32) {
        int v = (t < cnt) ? g_members[c * CAP + t] : 0x7fffffff;
        if (cnt <= 32) {
            #pragma unroll
            for (int k = 2; k <= 32; k <<= 1) {
                #pragma unroll
                for (int j = k >> 1; j > 0; j >>= 1) {
                    int other = __shfl_xor_sync(0xffffffffu, v, j);
                    bool up  = ((t & k) == 0);
                    bool low = ((t & j) == 0);
                    int mn = min(v, other), mx = max(v, other);
                    v = (low == up) ? mn : mx;
                }
            }
        }
        s_mem[t] = v;
    } else if (t >= 96 && t - 96 < CAP - 32) {
        int j = 32 + (t - 96);
        s_mem[j] = (j < cnt) ? g_members[c * CAP + j] : 0x7fffffff;
    }
    __syncthreads();

    float acc = 0.0f;
    int j = 0;
    for (; j + 4 <= cnt; j += 4) {
        float v0 = xs[(size_t)s_mem[j]   * DIM + t];
        float v1 = xs[(size_t)s_mem[j+1] * DIM + t];
        float v2 = xs[(size_t)s_mem[j+2] * DIM + t];
        float v3 = xs[(size_t)s_mem[j+3] * DIM + t];
        acc += v0; acc += v1; acc += v2; acc += v3;
    }
    for (; j < cnt; j++) acc += xs[(size_t)s_mem[j] * DIM + t];

    g_mus2[t * NC + c] = acc;     // [d][c]

    float a2 = acc * acc;
    #pragma unroll
    for (int o = 16; o > 0; o >>= 1) a2 += __shfl_xor_sync(0xffffffffu, a2, o);
    if ((t & 31) == 0) wsum[t >> 5] = a2;
    __syncthreads();
    if (t == 0) {
        g_m2[c]   = wsum[0] + wsum[1] + wsum[2] + wsum[3];
        g_cntf[c] = (float)g_cnt[c];
        g_cnt[c]  = 0;            // replay invariant
    }
}

// ---------------------------------------------------------------------------
// k2_loss: f32x2 register-tiled GEMM + logits + LSE + deterministic reduce.
// 128 threads, QB=4 queries/block, grid=512 (one full wave @ 4 blocks/SM).
// Thread t owns classes (2t, 2t+1) packed in f32x2 accumulators.
// ---------------------------------------------------------------------------
__device__ __forceinline__ unsigned long long
ffma2(unsigned long long a, unsigned long long b, unsigned long long c)
{
    unsigned long long d;
    asm("fma.rn.f32x2 %0, %1, %2, %3;" : "=l"(d) : "l"(a), "l"(b), "l"(c));
    return d;
}

__device__ __forceinline__ float
logit_fn(float s, float q2, float cnt, float m2, bool isy)
{
    float del = isy ? 1.0f : 0.0f;
    float dd  = cnt - del;
    float den = fmaxf(dd, 0.1f);
    float inv = 1.0f / den;
    float sp  = s - del * q2;
    float m2p = m2 - del * (2.0f * s - q2);
    float dist = q2 - 2.0f * sp * inv + m2p * inv * inv;
    return (dd > 0.1f) ? (-0.5f * dist) : 0.0f;
}

__global__ void __launch_bounds__(K2T, 4)
k2_loss(const float* __restrict__ xq, float* out, int N)
{
    __shared__ __align__(16) float2 xqdup[DIM][QB];   // 4 KB, (x,x) duplicated
    __shared__ float logits[QB][NC];                  // 4 KB
    __shared__ float q2s[QB];
    __shared__ int   ycls[QB];
    __shared__ float part[QB];
    __shared__ float red[K2T];
    __shared__ int   s_last;

    const int tid   = threadIdx.x;
    const int qbase = blockIdx.x * QB;
    const int q = tid >> 5, j = tid & 31;
    const int n = qbase + q;

    // stage query tile: warp w holds query w; duplicate into smem
    float4 v = make_float4(0.f, 0.f, 0.f, 0.f);
    if (n < N) v = reinterpret_cast<const float4*>(xq)[(size_t)n * 32 + j];
    xqdup[4*j+0][q] = make_float2(v.x, v.x);
    xqdup[4*j+1][q] = make_float2(v.y, v.y);
    xqdup[4*j+2][q] = make_float2(v.z, v.z);
    xqdup[4*j+3][q] = make_float2(v.w, v.w);
    float sq = v.x*v.x + v.y*v.y + v.z*v.z + v.w*v.w;
    #pragma unroll
    for (int o = 16; o > 0; o >>= 1) sq += __shfl_xor_sync(0xffffffffu, sq, o);
    if (j == 0) q2s[q] = sq;
    if (tid < QB) {
        int nn = qbase + tid;
        ycls[tid] = (nn < N) ? g_ys32[g_pos32[nn]] : 0;
    }
    __syncthreads();

    // mainloop: acc[q] = (s_{c0}, s_{c1}) via packed f32x2 FMA
    const unsigned long long* mup =
        reinterpret_cast<const unsigned long long*>(g_mus2);   // [d][pair]
    const ulonglong2* xd = reinterpret_cast<const ulonglong2*>(xqdup);

    unsigned long long a0 = 0ull, a1 = 0ull, a2 = 0ull, a3 = 0ull;
    #pragma unroll 8
    for (int d = 0; d < DIM; d++) {
        unsigned long long mu = mup[d * (NC / 2) + tid];   // LDG.64, L1-resident
        ulonglong2 x01 = xd[d * 2 + 0];                    // bcast LDS.128
        ulonglong2 x23 = xd[d * 2 + 1];
        a0 = ffma2(mu, x01.x, a0);
        a1 = ffma2(mu, x01.y, a1);
        a2 = ffma2(mu, x23.x, a2);
        a3 = ffma2(mu, x23.y, a3);
    }

    // epilogue: logits
    float2 cnt2 = reinterpret_cast<const float2*>(g_cntf)[tid];
    float2 m22  = reinterpret_cast<const float2*>(g_m2)[tid];
    const int c0 = 2 * tid, c1 = 2 * tid + 1;
    unsigned long long accs[QB] = {a0, a1, a2, a3};
    #pragma unroll
    for (int qq = 0; qq < QB; qq++) {
        float s0 = __uint_as_float((unsigned)(accs[qq] & 0xffffffffull));
        float s1 = __uint_as_float((unsigned)(accs[qq] >> 32));
        float qsq = q2s[qq];
        int   yc  = ycls[qq];
        float l0 = logit_fn(s0, qsq, cnt2.x, m22.x, c0 == yc);
        float l1 = logit_fn(s1, qsq, cnt2.y, m22.y, c1 == yc);
        reinterpret_cast<float2*>(&logits[qq][0])[tid] = make_float2(l0, l1);
    }
    __syncthreads();

    // LSE: warp w -> query w (8 classes/lane)
    {
        float vv[8];
        float m = -1e30f;
        #pragma unroll
        for (int k = 0; k < 8; k++) {
            vv[k] = logits[q][j + 32 * k];
            m = fmaxf(m, vv[k]);
        }
        #pragma unroll
        for (int o = 16; o > 0; o >>= 1) m = fmaxf(m, __shfl_xor_sync(0xffffffffu, m, o));
        float sum = 0.0f;
        #pragma unroll
        for (int k = 0; k < 8; k++) sum += __expf(vv[k] - m);
        #pragma unroll
        for (int o = 16; o > 0; o >>= 1) sum += __shfl_xor_sync(0xffffffffu, sum, o);
        if (j == 0)
            part[q] = (n < N) ? (m + __logf(sum) - logits[q][ycls[q]]) : 0.0f;
    }
    __syncthreads();

    // deterministic cross-block reduction via ticket-elected last block
    if (tid == 0) {
        g_part[blockIdx.x] = part[0] + part[1] + part[2] + part[3];
        __threadfence();
        int tk = atomicAdd(&g_ticket, 1);
        s_last = (tk == (int)gridDim.x - 1) ? 1 : 0;
    }
    __syncthreads();
    if (s_last) {
        float acc = 0.0f;
        for (int i = tid; i < (int)gridDim.x; i += K2T) acc += g_part[i];
        red[tid] = acc;
        __syncthreads();
        #pragma unroll
        for (int o = K2T / 2; o > 0; o >>= 1) {
            if (tid < o) red[tid] += red[tid + o];
            __syncthreads();
        }
        if (tid == 0) {
            out[0] = red[0] / (float)N;
            g_ticket = 0;   // replay invariant
        }
    }
}

// ---------------------------------------------------------------------------
extern "C" void kernel_launch(void* const* d_in, const int* in_sizes, int n_in,
                              void* d_out, int out_size)
{
    const float* xq  = (const float*)d_in[0];
    const float* xs  = (const float*)d_in[2];
    const void*  ys  = d_in[3];
    const void*  pos = d_in[4];
    float* out = (float*)d_out;

    int N = in_sizes[1];
    int S = in_sizes[3];
    if (N > N_MAX) N = N_MAX;
    if (S > S_MAX) S = S_MAX;

    k_build<<<64, 128>>>(ys, pos, S, N);
    k1_protos<<<NC, DIM>>>(xs);
    int nblk = (N + QB - 1) / QB;
    k2_loss<<<nblk, K2T>>>(xq, out, N);
}